// round 17
// baseline (speedup 1.0000x reference)
#include <cuda_runtime.h>
#include <cstdint>

// Problem constants
#define Bsz   16
#define Lseq  4096
#define Dd    512
#define SPB   8          // d-lanes per tile (full 32B sectors)
#define CH    17         // chunk length per thread
#define NCHB  128        // chunks per block per sequence
#define NTH   1024       // SPB * NCHB
#define LE    2176       // extended L-span per tile (2048 core + 128 halo)
#define LC    2048       // core L-span
#define YSTR  19         // padded per-thread stride in Y (gcd(19,32)=1)
#define TILES (Bsz*(Dd/SPB)*2)   // 2048

// smem floats: Y0+Y1 (2*NTH*YSTR) + RR(34 f2 = 68) + PW(16) + PK(8)
//            + VWT(528) + SWT(528) + XE(2*NTH) + CV(16)
#define SMEM_FLOATS (2*NTH*YSTR + 68 + 16 + 8 + 528 + 528 + 2*NTH + 16)

__device__ __forceinline__ void cp_async4(uint32_t dst, const float* src) {
    asm volatile("cp.async.ca.shared.global [%0], [%1], 4;" :: "r"(dst), "l"(src));
}

__global__ void __launch_bounds__(NTH, 1)
iir_filtfilt_kernel(const float* __restrict__ x,
                    const float* __restrict__ bc,
                    const float* __restrict__ am,
                    float* __restrict__ out)
{
    extern __shared__ float sm[];
    float*  Y0  = sm;                              // NTH*YSTR : x buffer A
    float*  Y1  = Y0 + NTH * YSTR;                 // NTH*YSTR : x buffer B
    float2* RR  = (float2*)(Y1 + NTH * YSTR);      // 17 used : row0(A^(i+1))
    float*  PW  = (float*)(RR + 34);               // 16 : A^17,A^34,A^51,A^68
    float*  PK  = PW + 16;                         // 8  : A^136, A^272
    float*  VWT = PK + 8;                          // 528 : warp aggregates [seq][w][2], stride 66
    float*  SWT = VWT + 528;                       // 528 : warp start states
    float*  XE  = SWT + 528;                       // 2*NTH : y-edges
    float*  CV  = XE + 2 * NTH;                    // 16 : fwd(8)+bwd(8) boundary consts

    uint32_t smem_u32;
    asm("{ .reg .u64 t0; cvta.to.shared.u64 t0, %1; cvt.u32.u64 %0, t0; }"
        : "=r"(smem_u32) : "l"(sm));
    const uint32_t Yu[2] = { smem_u32, smem_u32 + (uint32_t)(NTH * YSTR * 4) };

    const int tid  = threadIdx.x;
    const int lane = tid & 31;
    const int wrp  = tid >> 5;                     // 0..31
    const int seq  = tid & 7;                      // 0..7
    const int ch   = tid >> 3;                     // 0..127
    const int g    = lane >> 3;                    // chunk-in-warp 0..3

    const float b0  = bc[0], b1 = bc[1], b2 = bc[2];
    const float na1 = am[0], na2 = am[1];          // A row0 = (-a1,-a2)
    const float bsum = b0 + b1 + b2;               // == 0 exactly for this filter

    // Thread 0: RR[i]=row0(A^(i+1)) i<17; PW = A^17,A^34,A^51,A^68; PK = A^136,A^272.
    if (tid == 0) {
        float p00 = na1, p01 = na2, p10 = 1.f, p11 = 0.f;   // A^1
        RR[0] = make_float2(p00, p01);
        for (int i = 1; i < CH; ++i) {
            float q00 = fmaf(na1, p00, na2 * p10);
            float q01 = fmaf(na1, p01, na2 * p11);
            p10 = p00; p11 = p01; p00 = q00; p01 = q01;
            RR[i] = make_float2(p00, p01);
        }
        // p = A^17
        float a00 = p00, a01 = p01, a10 = p10, a11 = p11;
        PW[0] = a00; PW[1] = a01; PW[2] = a10; PW[3] = a11;            // A^17
        float b00 = a00*a00 + a01*a10, b01 = a00*a01 + a01*a11;        // A^34
        float b10 = a10*a00 + a11*a10, b11 = a10*a01 + a11*a11;
        PW[4] = b00; PW[5] = b01; PW[6] = b10; PW[7] = b11;
        float c00 = b00*a00 + b01*a10, c01 = b00*a01 + b01*a11;        // A^51
        float c10 = b10*a00 + b11*a10, c11 = b10*a01 + b11*a11;
        PW[8] = c00; PW[9] = c01; PW[10] = c10; PW[11] = c11;
        float d00 = b00*b00 + b01*b10, d01 = b00*b01 + b01*b11;        // A^68
        float d10 = b10*b00 + b11*b10, d11 = b10*b01 + b11*b11;
        PW[12] = d00; PW[13] = d01; PW[14] = d10; PW[15] = d11;
        float e00 = d00*d00 + d01*d10, e01 = d00*d01 + d01*d11;        // A^136
        float e10 = d10*d00 + d11*d10, e11 = d10*d01 + d11*d11;
        PK[0] = e00; PK[1] = e01; PK[2] = e10; PK[3] = e11;
        float f00 = e00*e00 + e01*e10, f01 = e00*e01 + e01*e11;        // A^272
        float f10 = e10*e00 + e11*e10, f11 = e10*e01 + e11*e11;
        PK[4] = f00; PK[5] = f01; PK[6] = f10; PK[7] = f11;
    }

    const size_t OUTT = (size_t)Bsz * Lseq * Dd;

    // Prologue: cp.async first tile's x into buffer 0.
    {
        int t0 = blockIdx.x;
        const int elo0 = (t0 & 1) ? (Lseq - LE) : 0;
        const float* xp0 = x + (size_t)(t0 >> 7) * Lseq * Dd
                             + (size_t)(elo0 + ch * CH) * Dd + (((t0 >> 1) & 63) * SPB) + seq;
        uint32_t dst = Yu[0] + (uint32_t)(tid * YSTR * 4);
        #pragma unroll
        for (int i = 0; i < CH; ++i)
            cp_async4(dst + 4u * i, xp0 + (size_t)i * Dd);
        asm volatile("cp.async.commit_group;" ::: "memory");
    }

    int buf = 0;
    for (int t = blockIdx.x; t < TILES; t += gridDim.x) {
        const int b    = t >> 7;                   // 128 tiles per batch
        const int dgrp = (t >> 1) & 63;
        const int h    = t & 1;                    // L-half 0/1
        const int d0   = dgrp * SPB;
        const int elo  = h ? (Lseq - LE) : 0;      // window start (1920 or 0)
        const int lbase = elo + ch * CH;           // this thread's first l

        float* Yc = buf ? Y1 : Y0;
        const uint32_t Ynext = Yu[buf ^ 1];

        // Wait for this tile's cp.async data; barrier makes it visible to all
        // threads AND orders prev tile's trend-reads before the next issues.
        asm volatile("cp.async.wait_group 0;" ::: "memory");
        __syncthreads();    // B1

        // Pull own chunk from smem to registers; halos read from neighbor chunk.
        float xr[CH];
        #pragma unroll
        for (int i = 0; i < CH; ++i) xr[i] = Yc[tid * YSTR + i];
        float xm1, xm2;
        if (ch == 0) { xm1 = xr[0]; xm2 = xr[0]; }          // edge/warm-up replicate
        else {
            xm1 = Yc[(tid - SPB) * YSTR + (CH - 1)];
            xm2 = Yc[(tid - SPB) * YSTR + (CH - 2)];
        }
        if (ch == 0) CV[seq] = bsum * xr[0];       // c_fwd (==0 exactly; visible by B3)

        // Next tile pointer (clamped self on the tail: harmless extra load).
        int t2 = t + gridDim.x;  if (t2 >= TILES) t2 = t;
        const int elo2 = (t2 & 1) ? (Lseq - LE) : 0;
        const float* xpn = x + (size_t)(t2 >> 7) * Lseq * Dd
                             + (size_t)(elo2 + ch * CH) * Dd + (((t2 >> 1) & 63) * SPB) + seq;
        const uint32_t dstn = Ynext + (uint32_t)(tid * YSTR * 4);

        // ---------------- forward zero-init scan (p0 -> xr) ------------------
        // One cp.async per iteration: paced through compute (proven placement).
        float s0 = 0.f, s1 = 0.f;
        #pragma unroll
        for (int i = 0; i < CH; ++i) {
            cp_async4(dstn + 4u * i, xpn + (size_t)i * Dd);
            float bx = fmaf(b2, xm2, fmaf(b1, xm1, b0 * xr[i]));
            xm2 = xm1; xm1 = xr[i];
            float ns = fmaf(na1, s0, fmaf(na2, s1, bx));
            s1 = s0; s0 = ns;
            xr[i] = ns;
        }
        asm volatile("cp.async.commit_group;" ::: "memory");

        // Intra-warp KS over the warp's 4 chunks: hops 1 (A^17), 2 (A^34).
        float v0 = s0, v1 = s1;
        #pragma unroll
        for (int st = 0; st < 2; ++st) {
            const int hc = 1 << st;
            const float* M = PW + 4 * (hc - 1) * (st ? 1 : 1);   // A^17 then A^34
            float m00 = PW[4*st + 0], m01 = PW[4*st + 1], m10 = PW[4*st + 2], m11 = PW[4*st + 3];
            float u0 = __shfl_up_sync(0xffffffffu, v0, 8 * hc);
            float u1 = __shfl_up_sync(0xffffffffu, v1, 8 * hc);
            if (g < hc) { u0 = 0.f; u1 = 0.f; }
            v0 = fmaf(m00, u0, fmaf(m01, u1, v0));
            v1 = fmaf(m10, u0, fmaf(m11, u1, v1));
            (void)M;
        }
        float E0 = __shfl_up_sync(0xffffffffu, v0, 8);
        float E1 = __shfl_up_sync(0xffffffffu, v1, 8);
        if (g == 0) { E0 = 0.f; E1 = 0.f; }
        if (g == 3) {
            VWT[seq * 66 + 2 * wrp]     = v0;
            VWT[seq * 66 + 2 * wrp + 1] = v1;
        }
        __syncthreads();    // B3

        // Inter-warp KS over 32 warp aggregates (warp s = seq s, all 32 lanes).
        // Hops 1,2,4 with A^68, A^136, A^272 (hop-8 terms ~3e-21: dropped).
        if (wrp < 8) {
            int s = wrp;
            float w0 = VWT[s * 66 + 2 * lane];
            float w1 = VWT[s * 66 + 2 * lane + 1];
            float c = CV[s];
            if (lane == 0) {                       // inject A^68 * [c,c]
                w0 = fmaf(PW[12] + PW[13], c, w0);
                w1 = fmaf(PW[14] + PW[15], c, w1);
            }
            #pragma unroll
            for (int st = 0; st < 3; ++st) {
                const int hc = 1 << st;
                float m00, m01, m10, m11;
                if (st == 0) { m00 = PW[12]; m01 = PW[13]; m10 = PW[14]; m11 = PW[15]; }
                else { m00 = PK[4*(st-1)]; m01 = PK[4*(st-1)+1]; m10 = PK[4*(st-1)+2]; m11 = PK[4*(st-1)+3]; }
                float u0 = __shfl_up_sync(0xffffffffu, w0, hc);
                float u1 = __shfl_up_sync(0xffffffffu, w1, hc);
                if (lane < hc) { u0 = 0.f; u1 = 0.f; }
                w0 = fmaf(m00, u0, fmaf(m01, u1, w0));
                w1 = fmaf(m10, u0, fmaf(m11, u1, w1));
            }
            float T0 = __shfl_up_sync(0xffffffffu, w0, 1);
            float T1 = __shfl_up_sync(0xffffffffu, w1, 1);
            if (lane == 0) { T0 = c; T1 = c; }
            SWT[s * 66 + 2 * lane]     = T0;
            SWT[s * 66 + 2 * lane + 1] = T1;
        }
        __syncthreads();    // B4

        // Forward start state: ss = A^(17g)·T_w + E_g ; publish y-edges.
        float ss0, ss1;
        {
            float T0 = SWT[seq * 66 + 2 * wrp], T1 = SWT[seq * 66 + 2 * wrp + 1];
            if (g == 0) { ss0 = T0; ss1 = T1; }
            else {
                const float* P = PW + 4 * (g - 1);
                ss0 = fmaf(P[0], T0, fmaf(P[1], T1, E0));
                ss1 = fmaf(P[2], T0, fmaf(P[3], T1, E1));
            }
        }
        float ylast = 0.f;
        {
            float2 r0 = RR[0], r1 = RR[1];
            XE[2 * tid]     = fmaf(r0.x, ss0, fmaf(r0.y, ss1, xr[0]));
            XE[2 * tid + 1] = fmaf(r1.x, ss0, fmaf(r1.y, ss1, xr[1]));
            if (ch == NCHB - 1) {
                float2 rl = RR[CH - 1];
                ylast = fmaf(rl.x, ss0, fmaf(rl.y, ss1, xr[CH - 1]));
                CV[8 + seq] = bsum * ylast;        // c_bwd (==0 exactly; exact at h=1)
            }
        }
        __syncthreads();    // B5

        // ---------------- backward zero-init scan (p0_bwd -> xr) -------------
        float yp1, yp2;
        if (ch == NCHB - 1) { yp1 = ylast; yp2 = ylast; }   // edge/warm-up replicate
        else { yp1 = XE[2*(tid+SPB)]; yp2 = XE[2*(tid+SPB)+1]; }
        s0 = 0.f; s1 = 0.f;
        #pragma unroll
        for (int i = CH - 1; i >= 0; --i) {
            float2 r = RR[i];
            float yv = fmaf(r.x, ss0, fmaf(r.y, ss1, xr[i]));
            float bx = fmaf(b2, yp2, fmaf(b1, yp1, b0 * yv));
            yp2 = yp1; yp1 = yv;
            float ns = fmaf(na1, s0, fmaf(na2, s1, bx));
            s1 = s0; s0 = ns;
            xr[i] = ns;
        }

        // Backward intra-warp KS (descending).
        v0 = s0; v1 = s1;
        #pragma unroll
        for (int st = 0; st < 2; ++st) {
            const int hc = 1 << st;
            float m00 = PW[4*st + 0], m01 = PW[4*st + 1], m10 = PW[4*st + 2], m11 = PW[4*st + 3];
            float u0 = __shfl_down_sync(0xffffffffu, v0, 8 * hc);
            float u1 = __shfl_down_sync(0xffffffffu, v1, 8 * hc);
            if (g > 3 - hc) { u0 = 0.f; u1 = 0.f; }
            v0 = fmaf(m00, u0, fmaf(m01, u1, v0));
            v1 = fmaf(m10, u0, fmaf(m11, u1, v1));
        }
        E0 = __shfl_down_sync(0xffffffffu, v0, 8);
        E1 = __shfl_down_sync(0xffffffffu, v1, 8);
        if (g == 3) { E0 = 0.f; E1 = 0.f; }
        if (g == 0) {
            VWT[seq * 66 + 2 * wrp]     = v0;
            VWT[seq * 66 + 2 * wrp + 1] = v1;
        }
        __syncthreads();    // B6

        // Backward inter-warp KS (mirror).
        if (wrp < 8) {
            int s = wrp;
            float w0 = VWT[s * 66 + 2 * lane];
            float w1 = VWT[s * 66 + 2 * lane + 1];
            float c = CV[8 + s];
            if (lane == 31) {
                w0 = fmaf(PW[12] + PW[13], c, w0);
                w1 = fmaf(PW[14] + PW[15], c, w1);
            }
            #pragma unroll
            for (int st = 0; st < 3; ++st) {
                const int hc = 1 << st;
                float m00, m01, m10, m11;
                if (st == 0) { m00 = PW[12]; m01 = PW[13]; m10 = PW[14]; m11 = PW[15]; }
                else { m00 = PK[4*(st-1)]; m01 = PK[4*(st-1)+1]; m10 = PK[4*(st-1)+2]; m11 = PK[4*(st-1)+3]; }
                float u0 = __shfl_down_sync(0xffffffffu, w0, hc);
                float u1 = __shfl_down_sync(0xffffffffu, w1, hc);
                if (lane > 31 - hc) { u0 = 0.f; u1 = 0.f; }
                w0 = fmaf(m00, u0, fmaf(m01, u1, w0));
                w1 = fmaf(m10, u0, fmaf(m11, u1, w1));
            }
            float T0 = __shfl_down_sync(0xffffffffu, w0, 1);
            float T1 = __shfl_down_sync(0xffffffffu, w1, 1);
            if (lane == 31) { T0 = c; T1 = c; }
            SWT[s * 66 + 2 * lane]     = T0;
            SWT[s * 66 + 2 * lane + 1] = T1;
        }
        __syncthreads();    // B7

        // Backward start state: sb = A^(17(3-g))·T'_w + E'_g.
        float sb0, sb1;
        {
            float T0 = SWT[seq * 66 + 2 * wrp], T1 = SWT[seq * 66 + 2 * wrp + 1];
            if (g == 3) { sb0 = T0; sb1 = T1; }
            else {
                const float* P = PW + 4 * (2 - g);
                sb0 = fmaf(P[0], T0, fmaf(P[1], T1, E0));
                sb1 = fmaf(P[2], T0, fmaf(P[3], T1, E1));
            }
        }

        // Final fix-up + predicated streaming stores (R12's exact form);
        // trend reads x from smem Y (protected by next iteration's B1).
        float* os = out + (size_t)b * Lseq * Dd + (size_t)lbase * Dd + d0 + seq;
        float* ot = os + OUTT;
        const int off = ch * CH - (h ? (LE - LC) : 0);
        #pragma unroll
        for (int i = 0; i < CH; ++i) {
            float2 r = RR[CH - 1 - i];
            float se = fmaf(r.x, sb0, fmaf(r.y, sb1, xr[i]));
            if ((unsigned)(off + i) < (unsigned)LC) {
                float xv = Yc[tid * YSTR + i];
                __stcs(os + (size_t)i * Dd, se);
                __stcs(ot + (size_t)i * Dd, xv - se);
            }
        }

        buf ^= 1;
    }
}

extern "C" void kernel_launch(void* const* d_in, const int* in_sizes, int n_in,
                              void* d_out, int out_size)
{
    const float* x  = (const float*)d_in[0];
    const float* bcp = (const float*)d_in[1];
    const float* amp = (const float*)d_in[2];
    float* out = (float*)d_out;

    int dev = 0;
    cudaGetDevice(&dev);
    int sms = 148;
    cudaDeviceGetAttribute(&sms, cudaDevAttrMultiProcessorCount, dev);

    int grid = sms;                        // persistent, 1 block/SM, double-buffered
    if (grid > TILES) grid = TILES;

    const size_t smem = (size_t)SMEM_FLOATS * sizeof(float);   // ~168.5 KB
    cudaFuncSetAttribute(iir_filtfilt_kernel,
                         cudaFuncAttributeMaxDynamicSharedMemorySize, (int)smem);

    iir_filtfilt_kernel<<<grid, NTH, smem>>>(x, bcp, amp, out);
}